// round 13
// baseline (speedup 1.0000x reference)
#include <cuda_runtime.h>
#include <cuda_fp16.h>
#include <cstdint>
#include <math.h>

// ---------------------------------------------------------------------------
#define M_TOK 32768      // B*S
#define NDIM  512        // E = O
#define DT_C  0.01f
#define NSTEPS 10

#define BM 128
#define BN 128
#define BK 32
#define NCHUNK 16        // 512/32
#define NTHR 128         // 4 warps, warp tile 64x64 (measured-best config)
#define NSTAGE 4
#define NTILES ((M_TOK / BM) * (NDIM / BN))   // 1024
#define NPERS 304                              // 152 SMs x 2 resident CTAs
#define WSZ (NDIM * NDIM)

// smem: rows of 80B (64B data + 16B pad -> conflict-free ldmatrix)
#define ROWB 80
#define TILE_BYTES (128 * ROWB)            // 10240
#define OFF_A  0
#define OFF_B  TILE_BYTES
#define STAGE_BYTES (2 * TILE_BYTES)       // 20480 (A+B)
#define SM_CTRL 4608                       // pad + bias[512] + fm[512]
#define GEMM_SMEM (SM_CTRL + NSTAGE * STAGE_BYTES)   // 86528; x2 CTAs = 173KB

// ---------------------------------------------------------------------------
// Global scratch (allocation-free rule)
// ---------------------------------------------------------------------------
__device__ __half g_act_a[M_TOK*NDIM];   // activations ping
__device__ __half g_act_b[M_TOK*NDIM];   // activations pong
__device__ float  g_ph[M_TOK*NDIM];      // fp32 phases for Kuramoto
__device__ __half g_w[4*NDIM*NDIM];      // transposed fp16 weights
__device__ unsigned g_bar_count;         // grid barrier arrive count
__device__ unsigned g_bar_gen;           // grid barrier generation

// ---------------------------------------------------------------------------
// PTX helpers (sm_80-era only)
// ---------------------------------------------------------------------------
static __device__ __forceinline__ uint32_t smem_u32(const void* p) {
    uint32_t a;
    asm("{ .reg .u64 t; cvta.to.shared.u64 t, %1; cvt.u32.u64 %0, t; }" : "=r"(a) : "l"(p));
    return a;
}
static __device__ __forceinline__ void cp16(uint32_t dst, const void* src) {
    asm volatile("cp.async.cg.shared.global [%0], [%1], 16;" :: "r"(dst), "l"(src));
}
#define CP_COMMIT() asm volatile("cp.async.commit_group;" ::: "memory")
#define CP_WAIT(n)  asm volatile("cp.async.wait_group %0;" :: "n"(n) : "memory")

#define LDSM4(r, addr) \
    asm volatile("ldmatrix.sync.aligned.m8n8.x4.shared.b16 {%0,%1,%2,%3}, [%4];" \
        : "=r"((r)[0]), "=r"((r)[1]), "=r"((r)[2]), "=r"((r)[3]) : "r"(addr))

static __device__ __forceinline__ void mma16816(float* c, const uint32_t* a,
                                                const uint32_t b0, const uint32_t b1) {
    asm volatile("mma.sync.aligned.m16n8k16.row.col.f32.f16.f16.f32 "
        "{%0,%1,%2,%3}, {%4,%5,%6,%7}, {%8,%9}, {%0,%1,%2,%3};"
        : "+f"(c[0]), "+f"(c[1]), "+f"(c[2]), "+f"(c[3])
        : "r"(a[0]), "r"(a[1]), "r"(a[2]), "r"(a[3]), "r"(b0), "r"(b1));
}

// fast tanh via MUFU: 1 - 2/(exp(2x)+1); saturates correctly at +-inf
static __device__ __forceinline__ float ftanh(float x) {
    float e, r;
    const float u = x * 2.8853900817779268f;   // 2*log2(e)
    asm("ex2.approx.f32 %0, %1;" : "=f"(e) : "f"(u));
    asm("rcp.approx.f32 %0, %1;" : "=f"(r) : "f"(e + 1.0f));
    return fmaf(-2.0f, r, 1.0f);
}

// ---------------------------------------------------------------------------
// Grid-wide barrier (all NPERS CTAs are co-resident by construction:
// __launch_bounds__(128,2), 173KB smem/SM, grid == 2*NumSMs).
// Generation-counting; state is self-consistent across graph replays.
// ---------------------------------------------------------------------------
static __device__ __forceinline__ void grid_sync() {
    __syncthreads();
    if (threadIdx.x == 0) {
        const unsigned gen = atomicAdd(&g_bar_gen, 0u);
        __threadfence();
        if (atomicAdd(&g_bar_count, 1u) == NPERS - 1u) {
            atomicExch(&g_bar_count, 0u);   // reset BEFORE release
            atomicAdd(&g_bar_gen, 1u);      // release
        } else {
            while (atomicAdd(&g_bar_gen, 0u) == gen) __nanosleep(64);
        }
        __threadfence();
    }
    __syncthreads();
}

// ---------------------------------------------------------------------------
// Load one K-chunk: A 128x32 fp16 + B 128x32 fp16. 8 cp16/thread (128 thr).
// ---------------------------------------------------------------------------
static __device__ __forceinline__ void load_chunk(
    uint32_t stage,
    const __half* __restrict__ A, const __half* __restrict__ B,
    int m0, int n0, int kc0, int tid)
{
#pragma unroll
    for (int i = 0; i < 4; i++) {
        const int t   = tid + i * NTHR;      // 0..511
        const int row = t >> 2;              // 0..127
        const int q   = t & 3;
        const uint32_t so = (uint32_t)(row * ROWB + q * 16);
        cp16(stage + OFF_A + so, A + (size_t)(m0 + row) * NDIM + kc0 + q * 8);
        cp16(stage + OFF_B + so, B + (size_t)(n0 + row) * NDIM + kc0 + q * 8);
    }
    CP_COMMIT();
}

// ---------------------------------------------------------------------------
// GEMM phase (R10 engine verbatim): C[M,N] = act(A @ B^T + bias)
// CTA 128x128, 4 warps of 64x64, 4-stage cp.async ring continuous across tiles,
// static tile walk t += NPERS, direct register->global epilogue.
// ---------------------------------------------------------------------------
template<int EPI>
static __device__ void gemm_phase(
    char* smem, uint32_t sb,
    const __half* __restrict__ A, const __half* __restrict__ B,
    const float* __restrict__ bias,
    __half* __restrict__ outH, float* __restrict__ outF,
    const float* __restrict__ noise, const float* __restrict__ alpha_p)
{
    const int tid  = threadIdx.x;
    const int wid  = tid >> 5;
    const int lane = tid & 31;
    const int wm = wid & 1;
    const int wn = wid >> 1;

    float* bias_s = (float*)(smem + 64);
    float* fm_s   = (float*)(smem + 2112);
    {
        const float alpha = (EPI == 3) ? *alpha_p : 0.f;
#pragma unroll
        for (int i = tid; i < NDIM; i += NTHR) {
            bias_s[i] = bias[i];
            if (EPI == 3) fm_s[i] = sinf(alpha * (float)i);
        }
    }

    int t  = blockIdx.x;
    int m0 = (t >> 2) * BM;
    int n0 = (t & 3) * BN;

    load_chunk(sb + SM_CTRL + 0 * STAGE_BYTES, A, B, m0, n0, 0 * BK, tid);
    load_chunk(sb + SM_CTRL + 1 * STAGE_BYTES, A, B, m0, n0, 1 * BK, tid);
    load_chunk(sb + SM_CTRL + 2 * STAGE_BYTES, A, B, m0, n0, 2 * BK, tid);

    const int g  = lane >> 3;
    const int lr = lane & 7;
    const uint32_t offA = (uint32_t)((wm * 64 + (g & 1) * 8 + lr) * ROWB + (g >> 1) * 16);
    const uint32_t offB = (uint32_t)((wn * 64 + (g >> 1) * 8 + lr) * ROWB + (g & 1) * 16);

    while (true) {
        const int tn  = t + NPERS;
        const bool has_next = (tn < NTILES);
        const int m0n = (tn >> 2) * BM;
        const int n0n = (tn & 3) * BN;

        float acc[4][8][4];
#pragma unroll
        for (int mt = 0; mt < 4; mt++)
#pragma unroll
            for (int nt = 0; nt < 8; nt++)
#pragma unroll
                for (int r = 0; r < 4; r++) acc[mt][nt][r] = 0.f;

#pragma unroll 1
        for (int c = 0; c < NCHUNK; c++) {
            CP_WAIT(2);
            __syncthreads();

            const int cc = c + 3;
            if (cc < NCHUNK)
                load_chunk(sb + SM_CTRL + (cc & 3) * STAGE_BYTES,
                           A, B, m0, n0, cc * BK, tid);
            else if (has_next)
                load_chunk(sb + SM_CTRL + (cc & 3) * STAGE_BYTES,
                           A, B, m0n, n0n, (cc - NCHUNK) * BK, tid);
            else
                CP_COMMIT();

            const uint32_t stage = sb + SM_CTRL + (c & 3) * STAGE_BYTES;
#pragma unroll
            for (int ks = 0; ks < 2; ks++) {
                uint32_t a[4][4], b[4][4];
#pragma unroll
                for (int mt = 0; mt < 4; mt++)
                    LDSM4(a[mt], stage + OFF_A + offA + mt * (16 * ROWB) + ks * 32);
#pragma unroll
                for (int bt = 0; bt < 4; bt++)
                    LDSM4(b[bt], stage + OFF_B + offB + bt * (16 * ROWB) + ks * 32);
#pragma unroll
                for (int mt = 0; mt < 4; mt++)
#pragma unroll
                    for (int nt = 0; nt < 8; nt++) {
                        const int bt = nt >> 1, sel = (nt & 1) * 2;
                        mma16816(acc[mt][nt], a[mt], b[bt][sel], b[bt][sel + 1]);
                    }
            }
        }

        // direct register -> global epilogue (overlaps next tile's loads)
        const int rbase = m0 + wm * 64 + (lane >> 2);
        const int cbase = n0 + wn * 64 + (lane & 3) * 2;
#pragma unroll
        for (int mt = 0; mt < 4; mt++)
#pragma unroll
            for (int nt = 0; nt < 8; nt++) {
                const int col = cbase + nt * 8;
#pragma unroll
                for (int h = 0; h < 2; h++) {
                    const int row = rbase + mt * 16 + h * 8;
                    float v0 = acc[mt][nt][h * 2 + 0] + bias_s[col + 0];
                    float v1 = acc[mt][nt][h * 2 + 1] + bias_s[col + 1];
                    const size_t e = (size_t)row * NDIM + col;
                    if (EPI == 1) {
                        *(__half2*)(outH + e) = __floats2half2_rn(ftanh(v0), ftanh(v1));
                    } else if (EPI == 2) {
                        *(__half2*)(outH + e) =
                            __floats2half2_rn(fmaxf(v0, 0.f), fmaxf(v1, 0.f));
                    } else if (EPI == 0) {
                        *(float2*)(outF + e) = make_float2(v0, v1);
                    } else {
                        const float2 nz = *(const float2*)(noise + e);
                        const float im0 = nz.x * fm_s[col + 0];
                        const float im1 = nz.y * fm_s[col + 1];
                        *(float4*)(outF + e * 4)       = make_float4(v0, im0, im0, im0);
                        *(float4*)(outF + (e + 1) * 4) = make_float4(v1, im1, im1, im1);
                    }
                }
            }

        if (!has_next) break;
        t = tn; m0 = m0n; n0 = n0n;
    }
    CP_WAIT(0);   // clean cp.async accounting before next phase
}

// ---------------------------------------------------------------------------
// Phase 0: weight transpose+fp16 (CTAs 0..63) || x -> fp16 (CTAs 64..303)
// ---------------------------------------------------------------------------
static __device__ void prep_phase(
    char* smem,
    const float* __restrict__ W1, const float* __restrict__ W2,
    const float* __restrict__ F1, const float* __restrict__ F2,
    __half* __restrict__ T,
    const float* __restrict__ x, __half* __restrict__ actA)
{
    const int tid = threadIdx.x;
    if (blockIdx.x < 64) {
        float* tile = (float*)(smem + SM_CTRL);   // 32x33 floats (4224 B)
        const int tx = tid & 31, ty = tid >> 5;   // 32 x 4
#pragma unroll 1
        for (int wt = blockIdx.x; wt < 1024; wt += 64) {
            const int z   = wt >> 8;
            const int rem = wt & 255;
            const float* W = (z == 0) ? W1 : (z == 1) ? W2 : (z == 2) ? F1 : F2;
            __half* Tz = T + (size_t)z * WSZ;
            const int bx = (rem & 15) * 32, by = (rem >> 4) * 32;
#pragma unroll
            for (int r = 0; r < 32; r += 4)
                tile[(ty + r) * 33 + tx] = W[(size_t)(by + ty + r) * NDIM + bx + tx];
            __syncthreads();
#pragma unroll
            for (int r = 0; r < 32; r += 4)
                Tz[(size_t)(bx + ty + r) * NDIM + by + tx] =
                    __float2half_rn(tile[tx * 33 + ty + r]);
            __syncthreads();   // protect tile reuse next iteration
        }
    } else {
        const int gt = (blockIdx.x - 64) * NTHR + tid;
        const int n4 = M_TOK * NDIM / 4;
#pragma unroll 1
        for (int i = gt; i < n4; i += 240 * NTHR) {
            const float4 v = *(const float4*)(x + (size_t)i * 4);
            __half2* O = (__half2*)(actA + (size_t)i * 4);
            O[0] = __floats2half2_rn(v.x, v.y);
            O[1] = __floats2half2_rn(v.z, v.w);
        }
    }
}

// ---------------------------------------------------------------------------
// Kuramoto phase: warp-per-token loop, 10 steps (rotation trick), fp16 out.
// ---------------------------------------------------------------------------
static __device__ void kuramoto_phase(
    const float* __restrict__ P, const float* __restrict__ omega,
    const float* __restrict__ Kp, __half* __restrict__ outH)
{
    const int lane  = threadIdx.x & 31;
    const int warp  = blockIdx.x * (NTHR / 32) + (threadIdx.x >> 5);
    const int nwarp = NPERS * (NTHR / 32);    // 1216
    const float Kv = *Kp;
    const float a_scale = DT_C * Kv * (1.0f / (float)NDIM);

    float w[16];
#pragma unroll
    for (int i = 0; i < 16; i++)
        w[i] = DT_C * omega[lane + 32 * i];   // token-invariant, hoisted

#pragma unroll 1
    for (int tok = warp; tok < M_TOK; tok += nwarp) {
        const float* ph = P + (size_t)tok * NDIM;
        float p[16], s[16], c[16];
#pragma unroll
        for (int i = 0; i < 16; i++) {
            p[i] = ph[lane + 32 * i];
            __sincosf(p[i], &s[i], &c[i]);
        }
#pragma unroll 1
        for (int step = 0; step < NSTEPS; step++) {
            float part = 0.f;
#pragma unroll
            for (int i = 0; i < 16; i++) part += s[i];
#pragma unroll
            for (int off = 16; off > 0; off >>= 1)
                part += __shfl_xor_sync(0xFFFFFFFFu, part, off);
            const float a = a_scale * part;
#pragma unroll
            for (int i = 0; i < 16; i++) {
                const float d  = fmaf(a, c[i], w[i]);
                p[i] += d;
                const float cd = fmaf(-0.5f * d, d, 1.0f);
                const float sn = fmaf(c[i],  d, s[i] * cd);
                const float cn = fmaf(-s[i], d, c[i] * cd);
                s[i] = sn; c[i] = cn;
            }
        }
        __half* oh = outH + (size_t)tok * NDIM;
#pragma unroll
        for (int i = 0; i < 16; i++)
            oh[lane + 32 * i] = __float2half_rn(p[i]);
    }
}

// ---------------------------------------------------------------------------
// Megakernel: prep || conv -> G1 -> G2 -> Kuramoto -> G3 -> G4
// ---------------------------------------------------------------------------
__global__ void __launch_bounds__(NTHR, 2)
mega(const float* __restrict__ x,
     const float* __restrict__ W1, const float* __restrict__ b1,
     const float* __restrict__ W2, const float* __restrict__ b2,
     const float* __restrict__ omega, const float* __restrict__ Kp,
     const float* __restrict__ alphap,
     const float* __restrict__ F1, const float* __restrict__ c1,
     const float* __restrict__ F2, const float* __restrict__ c2,
     const float* __restrict__ noise, float* __restrict__ out,
     __half* __restrict__ actA, __half* __restrict__ actB,
     __half* __restrict__ wT, float* __restrict__ phb)
{
    extern __shared__ char smem[];
    const uint32_t sb = smem_u32(smem);

    prep_phase(smem, W1, W2, F1, F2, wT, x, actA);
    grid_sync();
    // phases = tanh(x @ W1 + b1) -> fp16
    gemm_phase<1>(smem, sb, actA, wT + 0 * WSZ, b1, actB, nullptr, nullptr, nullptr);
    grid_sync();
    // phases = phases @ W2 + b2 -> fp32
    gemm_phase<0>(smem, sb, actB, wT + 1 * WSZ, b2, nullptr, phb, nullptr, nullptr);
    grid_sync();
    // Kuramoto -> fp16 phases
    kuramoto_phase(phb, omega, Kp, actA);
    grid_sync();
    // h = relu(phases @ F1 + c1) -> fp16
    gemm_phase<2>(smem, sb, actA, wT + 2 * WSZ, c1, actB, nullptr, nullptr, nullptr);
    grid_sync();
    // out = expand(h @ F2 + c2, noise)
    gemm_phase<3>(smem, sb, actB, wT + 3 * WSZ, c2, nullptr, out, noise, alphap);
}

// ---------------------------------------------------------------------------
extern "C" void kernel_launch(void* const* d_in, const int* in_sizes, int n_in,
                              void* d_out, int out_size)
{
    const float* x      = (const float*)d_in[0];
    const float* W1     = (const float*)d_in[1];
    const float* b1     = (const float*)d_in[2];
    const float* W2     = (const float*)d_in[3];
    const float* b2     = (const float*)d_in[4];
    const float* omega  = (const float*)d_in[5];
    const float* Kp     = (const float*)d_in[6];
    const float* alphap = (const float*)d_in[7];
    const float* F1     = (const float*)d_in[8];
    const float* c1     = (const float*)d_in[9];
    const float* F2     = (const float*)d_in[10];
    const float* c2     = (const float*)d_in[11];
    const float* noise  = (const float*)d_in[12];
    float* out = (float*)d_out;

    __half *actA, *actB, *wT;
    float* phb;
    cudaGetSymbolAddress((void**)&actA, g_act_a);
    cudaGetSymbolAddress((void**)&actB, g_act_b);
    cudaGetSymbolAddress((void**)&wT,   g_w);
    cudaGetSymbolAddress((void**)&phb,  g_ph);

    cudaFuncSetAttribute(mega, cudaFuncAttributeMaxDynamicSharedMemorySize, GEMM_SMEM);

    mega<<<NPERS, NTHR, GEMM_SMEM>>>(x, W1, b1, W2, b2, omega, Kp, alphap,
                                     F1, c1, F2, c2, noise, out,
                                     actA, actB, wT, phb);
}

// round 14
// speedup vs baseline: 1.2140x; 1.2140x over previous
#include <cuda_runtime.h>
#include <cuda_fp16.h>
#include <cstdint>
#include <math.h>

// ---------------------------------------------------------------------------
#define M_TOK 32768      // B*S
#define NDIM  512        // E = O
#define DT_C  0.01f
#define NSTEPS 10

#define BM 128
#define BN 128
#define BK 32
#define NCHUNK 16        // 512/32
#define NTHR 128         // 4 warps, warp tile 64x64 (measured-best config)
#define NSTAGE 4
#define NTILES ((M_TOK / BM) * (NDIM / BN))   // 1024
#define NPERS 304                              // 152 SMs x 2 resident CTAs
#define WSZ (NDIM * NDIM)

// smem: rows of 80B (64B data + 16B pad -> conflict-free ldmatrix)
#define ROWB 80
#define TILE_BYTES (128 * ROWB)            // 10240
#define OFF_A  0
#define OFF_B  TILE_BYTES
#define STAGE_BYTES (2 * TILE_BYTES)       // 20480 (A+B)
#define SM_CTRL 4608                       // pad + bias[512] + fm[512]
#define GEMM_SMEM (SM_CTRL + NSTAGE * STAGE_BYTES)   // 86528; x2 CTAs = 173KB

// ---------------------------------------------------------------------------
// Global scratch (allocation-free rule)
// ---------------------------------------------------------------------------
__device__ __half g_act_a[M_TOK*NDIM];   // activations ping
__device__ __half g_act_b[M_TOK*NDIM];   // activations pong
__device__ float  g_ph[M_TOK*NDIM];      // fp32 phases for Kuramoto
__device__ __half g_w[4*NDIM*NDIM];      // transposed fp16 weights

// ---------------------------------------------------------------------------
// PTX helpers (sm_80-era only)
// ---------------------------------------------------------------------------
static __device__ __forceinline__ uint32_t smem_u32(const void* p) {
    uint32_t a;
    asm("{ .reg .u64 t; cvta.to.shared.u64 t, %1; cvt.u32.u64 %0, t; }" : "=r"(a) : "l"(p));
    return a;
}
static __device__ __forceinline__ void cp16(uint32_t dst, const void* src) {
    asm volatile("cp.async.cg.shared.global [%0], [%1], 16;" :: "r"(dst), "l"(src));
}
#define CP_COMMIT() asm volatile("cp.async.commit_group;" ::: "memory")
#define CP_WAIT(n)  asm volatile("cp.async.wait_group %0;" :: "n"(n) : "memory")

#define LDSM4(r, addr) \
    asm volatile("ldmatrix.sync.aligned.m8n8.x4.shared.b16 {%0,%1,%2,%3}, [%4];" \
        : "=r"((r)[0]), "=r"((r)[1]), "=r"((r)[2]), "=r"((r)[3]) : "r"(addr))

static __device__ __forceinline__ void mma16816(float* c, const uint32_t* a,
                                                const uint32_t b0, const uint32_t b1) {
    asm volatile("mma.sync.aligned.m16n8k16.row.col.f32.f16.f16.f32 "
        "{%0,%1,%2,%3}, {%4,%5,%6,%7}, {%8,%9}, {%0,%1,%2,%3};"
        : "+f"(c[0]), "+f"(c[1]), "+f"(c[2]), "+f"(c[3])
        : "r"(a[0]), "r"(a[1]), "r"(a[2]), "r"(a[3]), "r"(b0), "r"(b1));
}

// fast tanh via MUFU: 1 - 2/(exp(2x)+1); saturates correctly at +-inf
static __device__ __forceinline__ float ftanh(float x) {
    float e, r;
    const float u = x * 2.8853900817779268f;   // 2*log2(e)
    asm("ex2.approx.f32 %0, %1;" : "=f"(e) : "f"(u));
    asm("rcp.approx.f32 %0, %1;" : "=f"(r) : "f"(e + 1.0f));
    return fmaf(-2.0f, r, 1.0f);
}

// ---------------------------------------------------------------------------
// Load one K-chunk: A 128x32 fp16 + B 128x32 fp16. 8 cp16/thread (128 thr).
// ---------------------------------------------------------------------------
static __device__ __forceinline__ void load_chunk(
    uint32_t stage,
    const __half* __restrict__ A, const __half* __restrict__ B,
    int m0, int n0, int kc0, int tid)
{
#pragma unroll
    for (int i = 0; i < 4; i++) {
        const int t   = tid + i * NTHR;      // 0..511
        const int row = t >> 2;              // 0..127
        const int q   = t & 3;
        const uint32_t so = (uint32_t)(row * ROWB + q * 16);
        cp16(stage + OFF_A + so, A + (size_t)(m0 + row) * NDIM + kc0 + q * 8);
        cp16(stage + OFF_B + so, B + (size_t)(n0 + row) * NDIM + kc0 + q * 8);
    }
    CP_COMMIT();
}

// ---------------------------------------------------------------------------
// Persistent fp16 GEMM (R10 engine): C[M,N] = act(A @ B^T + bias)
// CTA 128x128, 4 warps of 64x64, 4-stage cp.async ring continuous across tiles,
// static tile walk t += NPERS, direct register->global epilogue.
// EPI: 0 -> fp32 outF; 1 -> tanh fp16 outH; 2 -> relu fp16 outH;
//      3 -> final [m,n,4] {v, im, im, im}, im = noise*sin(alpha*n)
// ---------------------------------------------------------------------------
template<int EPI>
__global__ void __launch_bounds__(NTHR, 2)
gemm_f16(const __half* __restrict__ A, const __half* __restrict__ B,
         const float* __restrict__ bias,
         __half* __restrict__ outH, float* __restrict__ outF,
         const float* __restrict__ noise, const float* __restrict__ alpha_p)
{
    extern __shared__ char smem[];
    const uint32_t sb = smem_u32(smem);
    const int tid  = threadIdx.x;
    const int wid  = tid >> 5;
    const int lane = tid & 31;

    const int wm = wid & 1;        // 2 warps along M (64 rows each)
    const int wn = wid >> 1;       // 2 warps along N (64 cols each)

    float* bias_s = (float*)(smem + 64);      // 512 floats
    float* fm_s   = (float*)(smem + 2112);    // 512 floats
    {
        const float alpha = (EPI == 3) ? *alpha_p : 0.f;
#pragma unroll
        for (int i = tid; i < NDIM; i += NTHR) {
            bias_s[i] = bias[i];
            if (EPI == 3) fm_s[i] = sinf(alpha * (float)i);
        }
    }

    int t  = blockIdx.x;
    int m0 = (t >> 2) * BM;
    int n0 = (t & 3) * BN;

    // prologue: 3 chunk-loads of first tile in flight
    load_chunk(sb + SM_CTRL + 0 * STAGE_BYTES, A, B, m0, n0, 0 * BK, tid);
    load_chunk(sb + SM_CTRL + 1 * STAGE_BYTES, A, B, m0, n0, 1 * BK, tid);
    load_chunk(sb + SM_CTRL + 2 * STAGE_BYTES, A, B, m0, n0, 2 * BK, tid);

    const int g  = lane >> 3;
    const int lr = lane & 7;
    const uint32_t offA = (uint32_t)((wm * 64 + (g & 1) * 8 + lr) * ROWB + (g >> 1) * 16);
    const uint32_t offB = (uint32_t)((wn * 64 + (g >> 1) * 8 + lr) * ROWB + (g & 1) * 16);

    while (true) {
        const int tn  = t + NPERS;
        const bool has_next = (tn < NTILES);
        const int m0n = (tn >> 2) * BM;
        const int n0n = (tn & 3) * BN;

        float acc[4][8][4];
#pragma unroll
        for (int mt = 0; mt < 4; mt++)
#pragma unroll
            for (int nt = 0; nt < 8; nt++)
#pragma unroll
                for (int r = 0; r < 4; r++) acc[mt][nt][r] = 0.f;

#pragma unroll 1
        for (int c = 0; c < NCHUNK; c++) {
            CP_WAIT(2);             // chunk c landed (c+1, c+2 pending)
            __syncthreads();        // all warps done with chunk c-1

            const int cc = c + 3;   // refill the slot chunk c-1 vacated
            if (cc < NCHUNK)
                load_chunk(sb + SM_CTRL + (cc & 3) * STAGE_BYTES,
                           A, B, m0, n0, cc * BK, tid);
            else if (has_next)
                load_chunk(sb + SM_CTRL + (cc & 3) * STAGE_BYTES,
                           A, B, m0n, n0n, (cc - NCHUNK) * BK, tid);
            else
                CP_COMMIT();        // empty group keeps accounting exact

            const uint32_t stage = sb + SM_CTRL + (c & 3) * STAGE_BYTES;
#pragma unroll
            for (int ks = 0; ks < 2; ks++) {
                uint32_t a[4][4], b[4][4];
#pragma unroll
                for (int mt = 0; mt < 4; mt++)
                    LDSM4(a[mt], stage + OFF_A + offA + mt * (16 * ROWB) + ks * 32);
#pragma unroll
                for (int bt = 0; bt < 4; bt++)
                    LDSM4(b[bt], stage + OFF_B + offB + bt * (16 * ROWB) + ks * 32);
#pragma unroll
                for (int mt = 0; mt < 4; mt++)
#pragma unroll
                    for (int nt = 0; nt < 8; nt++) {
                        const int bt = nt >> 1, sel = (nt & 1) * 2;
                        mma16816(acc[mt][nt], a[mt], b[bt][sel], b[bt][sel + 1]);
                    }
            }
        }

        // ---- epilogue: direct register -> global (overlaps next tile's loads)
        const int rbase = m0 + wm * 64 + (lane >> 2);
        const int cbase = n0 + wn * 64 + (lane & 3) * 2;
#pragma unroll
        for (int mt = 0; mt < 4; mt++)
#pragma unroll
            for (int nt = 0; nt < 8; nt++) {
                const int col = cbase + nt * 8;
#pragma unroll
                for (int h = 0; h < 2; h++) {
                    const int row = rbase + mt * 16 + h * 8;
                    float v0 = acc[mt][nt][h * 2 + 0] + bias_s[col + 0];
                    float v1 = acc[mt][nt][h * 2 + 1] + bias_s[col + 1];
                    const size_t e = (size_t)row * NDIM + col;
                    if (EPI == 1) {
                        *(__half2*)(outH + e) = __floats2half2_rn(ftanh(v0), ftanh(v1));
                    } else if (EPI == 2) {
                        *(__half2*)(outH + e) =
                            __floats2half2_rn(fmaxf(v0, 0.f), fmaxf(v1, 0.f));
                    } else if (EPI == 0) {
                        *(float2*)(outF + e) = make_float2(v0, v1);
                    } else {
                        const float2 nz = *(const float2*)(noise + e);
                        const float im0 = nz.x * fm_s[col + 0];
                        const float im1 = nz.y * fm_s[col + 1];
                        *(float4*)(outF + e * 4)       = make_float4(v0, im0, im0, im0);
                        *(float4*)(outF + (e + 1) * 4) = make_float4(v1, im1, im1, im1);
                    }
                }
            }

        if (!has_next) break;
        t = tn; m0 = m0n; n0 = n0n;
    }
}

// ---------------------------------------------------------------------------
// Merged prep: CTAs 0..1023 transpose+convert the 4 weights (one 32x32 tile
// each); CTAs 1024..3071 convert x -> fp16 (grid-stride). One launch, the two
// halves run concurrently (no data dependence).
// ---------------------------------------------------------------------------
__global__ void __launch_bounds__(256)
prep(const float* __restrict__ W1, const float* __restrict__ W2,
     const float* __restrict__ F1, const float* __restrict__ F2,
     __half* __restrict__ T,
     const float* __restrict__ x, __half* __restrict__ actA)
{
    const int tid = threadIdx.x;
    const int b   = blockIdx.x;

    if (b < 1024) {
        const int z   = b >> 8;             // which weight
        const int rem = b & 255;            // tile within it
        const float* W = (z == 0) ? W1 : (z == 1) ? W2 : (z == 2) ? F1 : F2;
        __half* Tz = T + (size_t)z * WSZ;

        __shared__ float tile[32][33];
        const int bx = (rem & 15) * 32, by = (rem >> 4) * 32;
        const int tx = tid & 31, ty = tid >> 5;   // 32 x 8
#pragma unroll
        for (int r = 0; r < 32; r += 8)
            tile[ty + r][tx] = W[(size_t)(by + ty + r) * NDIM + bx + tx];
        __syncthreads();
#pragma unroll
        for (int r = 0; r < 32; r += 8)
            Tz[(size_t)(bx + ty + r) * NDIM + by + tx] =
                __float2half_rn(tile[tx][ty + r]);
    } else {
        const int gt = (b - 1024) * 256 + tid;
        const int n4 = M_TOK * NDIM / 4;
#pragma unroll 2
        for (int i = gt; i < n4; i += 2048 * 256) {
            const float4 v = *(const float4*)(x + (size_t)i * 4);
            __half2* O = (__half2*)(actA + (size_t)i * 4);
            O[0] = __floats2half2_rn(v.x, v.y);
            O[1] = __floats2half2_rn(v.z, v.w);
        }
    }
}

// ---------------------------------------------------------------------------
// Kuramoto: 10 steps (rotation trick), emits fp16 phases
// ---------------------------------------------------------------------------
__global__ void __launch_bounds__(256)
kuramoto_kernel(const float* __restrict__ P, const float* __restrict__ omega,
                const float* __restrict__ Kp, __half* __restrict__ outH)
{
    const int gwarp = (blockIdx.x * blockDim.x + threadIdx.x) >> 5;
    const int lane  = threadIdx.x & 31;
    if (gwarp >= M_TOK) return;

    const float* ph = P + (size_t)gwarp * NDIM;
    const float Kv = *Kp;
    const float a_scale = DT_C * Kv * (1.0f / (float)NDIM);

    float p[16], s[16], c[16], w[16];
#pragma unroll
    for (int i = 0; i < 16; i++) {
        const int e = lane + 32 * i;
        p[i] = ph[e];
        w[i] = DT_C * omega[e];
        __sincosf(p[i], &s[i], &c[i]);   // MUFU; |p| ~ O(3), err ~1e-6
    }
#pragma unroll 1
    for (int step = 0; step < NSTEPS; step++) {
        float part = 0.f;
#pragma unroll
        for (int i = 0; i < 16; i++) part += s[i];
#pragma unroll
        for (int off = 16; off > 0; off >>= 1)
            part += __shfl_xor_sync(0xFFFFFFFFu, part, off);
        const float a = a_scale * part;
#pragma unroll
        for (int i = 0; i < 16; i++) {
            const float d  = fmaf(a, c[i], w[i]);
            p[i] += d;
            const float cd = fmaf(-0.5f * d, d, 1.0f);
            const float sn = fmaf(c[i],  d, s[i] * cd);
            const float cn = fmaf(-s[i], d, c[i] * cd);
            s[i] = sn; c[i] = cn;
        }
    }
    const size_t base = (size_t)gwarp * NDIM;
#pragma unroll
    for (int i = 0; i < 16; i++)
        outH[base + lane + 32 * i] = __float2half_rn(p[i]);
}

// ---------------------------------------------------------------------------
extern "C" void kernel_launch(void* const* d_in, const int* in_sizes, int n_in,
                              void* d_out, int out_size)
{
    const float* x      = (const float*)d_in[0];
    const float* W1     = (const float*)d_in[1];
    const float* b1     = (const float*)d_in[2];
    const float* W2     = (const float*)d_in[3];
    const float* b2     = (const float*)d_in[4];
    const float* omega  = (const float*)d_in[5];
    const float* Kp     = (const float*)d_in[6];
    const float* alphap = (const float*)d_in[7];
    const float* F1     = (const float*)d_in[8];
    const float* c1     = (const float*)d_in[9];
    const float* F2     = (const float*)d_in[10];
    const float* c2     = (const float*)d_in[11];
    const float* noise  = (const float*)d_in[12];
    float* out = (float*)d_out;

    __half *actA, *actB, *wT;
    float* phb;
    cudaGetSymbolAddress((void**)&actA, g_act_a);
    cudaGetSymbolAddress((void**)&actB, g_act_b);
    cudaGetSymbolAddress((void**)&wT,   g_w);
    cudaGetSymbolAddress((void**)&phb,  g_ph);

    cudaFuncSetAttribute(gemm_f16<0>, cudaFuncAttributeMaxDynamicSharedMemorySize, GEMM_SMEM);
    cudaFuncSetAttribute(gemm_f16<1>, cudaFuncAttributeMaxDynamicSharedMemorySize, GEMM_SMEM);
    cudaFuncSetAttribute(gemm_f16<2>, cudaFuncAttributeMaxDynamicSharedMemorySize, GEMM_SMEM);
    cudaFuncSetAttribute(gemm_f16<3>, cudaFuncAttributeMaxDynamicSharedMemorySize, GEMM_SMEM);

    // prep: weights transpose (CTAs 0..1023) || x conversion (CTAs 1024..3071)
    prep<<<3072, 256>>>(W1, W2, F1, F2, wT, x, actA);

    // phases = tanh(x @ W1 + b1) -> fp16
    gemm_f16<1><<<NPERS, NTHR, GEMM_SMEM>>>(actA, wT + 0*WSZ,
                                            b1, actB, nullptr, nullptr, nullptr);
    // phases = phases @ W2 + b2 -> fp32
    gemm_f16<0><<<NPERS, NTHR, GEMM_SMEM>>>(actB, wT + 1*WSZ,
                                            b2, nullptr, phb, nullptr, nullptr);
    // Kuramoto -> fp16 phases
    kuramoto_kernel<<<M_TOK / 8, 256>>>(phb, omega, Kp, actA);
    // h = relu(phases @ F1 + c1) -> fp16
    gemm_f16<2><<<NPERS, NTHR, GEMM_SMEM>>>(actA, wT + 2*WSZ,
                                            c1, actB, nullptr, nullptr, nullptr);
    // out = expand(h @ F2 + c2, noise)
    gemm_f16<3><<<NPERS, NTHR, GEMM_SMEM>>>(actB, wT + 3*WSZ,
                                            c2, nullptr, out, noise, alphap);
}

// round 15
// speedup vs baseline: 1.2535x; 1.0325x over previous
#include <cuda_runtime.h>
#include <cuda_fp16.h>
#include <cstdint>
#include <math.h>

// ---------------------------------------------------------------------------
#define M_TOK 32768      // B*S
#define NDIM  512        // E = O
#define DT_C  0.01f
#define NSTEPS 10

#define BM 128
#define BN 128
#define BK 32
#define NCHUNK 16        // 512/32
#define NTHR 128         // 4 warps, warp tile 64x64 (measured-best config)
#define NSTAGE 4
#define NTILES ((M_TOK / BM) * (NDIM / BN))   // 1024
#define NPERS 304                              // 152 SMs x 2 resident CTAs
#define WSZ (NDIM * NDIM)

// smem: rows of 80B (64B data + 16B pad -> conflict-free ldmatrix)
#define ROWB 80
#define TILE_BYTES (128 * ROWB)            // 10240
#define OFF_A  0
#define OFF_B  TILE_BYTES
#define STAGE_BYTES (2 * TILE_BYTES)       // 20480 (A+B)
#define SM_CTRL 4608                       // pad + bias[512] + fm[512]
#define GEMM_SMEM (SM_CTRL + NSTAGE * STAGE_BYTES)   // 86528; x2 CTAs = 173KB

// ---------------------------------------------------------------------------
// Global scratch (allocation-free rule)
// ---------------------------------------------------------------------------
__device__ __half g_act_a[M_TOK*NDIM];   // activations ping
__device__ __half g_act_b[M_TOK*NDIM];   // activations pong
__device__ float  g_ph[M_TOK*NDIM];      // fp32 phases for Kuramoto
__device__ __half g_w[4*NDIM*NDIM];      // transposed fp16 weights

// ---------------------------------------------------------------------------
// PTX helpers (sm_80-era only)
// ---------------------------------------------------------------------------
static __device__ __forceinline__ uint32_t smem_u32(const void* p) {
    uint32_t a;
    asm("{ .reg .u64 t; cvta.to.shared.u64 t, %1; cvt.u32.u64 %0, t; }" : "=r"(a) : "l"(p));
    return a;
}
static __device__ __forceinline__ void cp16(uint32_t dst, const void* src) {
    asm volatile("cp.async.cg.shared.global [%0], [%1], 16;" :: "r"(dst), "l"(src));
}
#define CP_COMMIT() asm volatile("cp.async.commit_group;" ::: "memory")
#define CP_WAIT(n)  asm volatile("cp.async.wait_group %0;" :: "n"(n) : "memory")

#define LDSM4(r, addr) \
    asm volatile("ldmatrix.sync.aligned.m8n8.x4.shared.b16 {%0,%1,%2,%3}, [%4];" \
        : "=r"((r)[0]), "=r"((r)[1]), "=r"((r)[2]), "=r"((r)[3]) : "r"(addr))

static __device__ __forceinline__ void mma16816(float* c, const uint32_t* a,
                                                const uint32_t b0, const uint32_t b1) {
    asm volatile("mma.sync.aligned.m16n8k16.row.col.f32.f16.f16.f32 "
        "{%0,%1,%2,%3}, {%4,%5,%6,%7}, {%8,%9}, {%0,%1,%2,%3};"
        : "+f"(c[0]), "+f"(c[1]), "+f"(c[2]), "+f"(c[3])
        : "r"(a[0]), "r"(a[1]), "r"(a[2]), "r"(a[3]), "r"(b0), "r"(b1));
}

// fast tanh via MUFU: 1 - 2/(exp(2x)+1); saturates correctly at +-inf
static __device__ __forceinline__ float ftanh(float x) {
    float e, r;
    const float u = x * 2.8853900817779268f;   // 2*log2(e)
    asm("ex2.approx.f32 %0, %1;" : "=f"(e) : "f"(u));
    asm("rcp.approx.f32 %0, %1;" : "=f"(r) : "f"(e + 1.0f));
    return fmaf(-2.0f, r, 1.0f);
}

// ---------------------------------------------------------------------------
// Load one K-chunk: A 128x32 fp16 + B 128x32 fp16. 8 cp16/thread (128 thr).
// ---------------------------------------------------------------------------
static __device__ __forceinline__ void load_chunk(
    uint32_t stage,
    const __half* __restrict__ A, const __half* __restrict__ B,
    int m0, int n0, int kc0, int tid)
{
#pragma unroll
    for (int i = 0; i < 4; i++) {
        const int t   = tid + i * NTHR;      // 0..511
        const int row = t >> 2;              // 0..127
        const int q   = t & 3;
        const uint32_t so = (uint32_t)(row * ROWB + q * 16);
        cp16(stage + OFF_A + so, A + (size_t)(m0 + row) * NDIM + kc0 + q * 8);
        cp16(stage + OFF_B + so, B + (size_t)(n0 + row) * NDIM + kc0 + q * 8);
    }
    CP_COMMIT();
}

// ---------------------------------------------------------------------------
// Persistent fp16 GEMM (R10 engine, frozen): C[M,N] = act(A @ B^T + bias)
// CTA 128x128, 4 warps of 64x64, 4-stage cp.async ring continuous across tiles,
// static tile walk t += NPERS, direct register->global epilogue.
// EPI: 0 -> fp32 outF; 1 -> tanh fp16 outH; 2 -> relu fp16 outH;
//      3 -> final [m,n,4] {v, im, im, im}, im = noise*sin(alpha*n)
// ---------------------------------------------------------------------------
template<int EPI>
__global__ void __launch_bounds__(NTHR, 2)
gemm_f16(const __half* __restrict__ A, const __half* __restrict__ B,
         const float* __restrict__ bias,
         __half* __restrict__ outH, float* __restrict__ outF,
         const float* __restrict__ noise, const float* __restrict__ alpha_p)
{
    extern __shared__ char smem[];
    const uint32_t sb = smem_u32(smem);
    const int tid  = threadIdx.x;
    const int wid  = tid >> 5;
    const int lane = tid & 31;

    const int wm = wid & 1;        // 2 warps along M (64 rows each)
    const int wn = wid >> 1;       // 2 warps along N (64 cols each)

    float* bias_s = (float*)(smem + 64);      // 512 floats
    float* fm_s   = (float*)(smem + 2112);    // 512 floats
    {
        const float alpha = (EPI == 3) ? *alpha_p : 0.f;
#pragma unroll
        for (int i = tid; i < NDIM; i += NTHR) {
            bias_s[i] = bias[i];
            if (EPI == 3) fm_s[i] = sinf(alpha * (float)i);
        }
    }

    int t  = blockIdx.x;
    int m0 = (t >> 2) * BM;
    int n0 = (t & 3) * BN;

    // prologue: 3 chunk-loads of first tile in flight
    load_chunk(sb + SM_CTRL + 0 * STAGE_BYTES, A, B, m0, n0, 0 * BK, tid);
    load_chunk(sb + SM_CTRL + 1 * STAGE_BYTES, A, B, m0, n0, 1 * BK, tid);
    load_chunk(sb + SM_CTRL + 2 * STAGE_BYTES, A, B, m0, n0, 2 * BK, tid);

    const int g  = lane >> 3;
    const int lr = lane & 7;
    const uint32_t offA = (uint32_t)((wm * 64 + (g & 1) * 8 + lr) * ROWB + (g >> 1) * 16);
    const uint32_t offB = (uint32_t)((wn * 64 + (g >> 1) * 8 + lr) * ROWB + (g & 1) * 16);

    while (true) {
        const int tn  = t + NPERS;
        const bool has_next = (tn < NTILES);
        const int m0n = (tn >> 2) * BM;
        const int n0n = (tn & 3) * BN;

        float acc[4][8][4];
#pragma unroll
        for (int mt = 0; mt < 4; mt++)
#pragma unroll
            for (int nt = 0; nt < 8; nt++)
#pragma unroll
                for (int r = 0; r < 4; r++) acc[mt][nt][r] = 0.f;

#pragma unroll 1
        for (int c = 0; c < NCHUNK; c++) {
            CP_WAIT(2);             // chunk c landed (c+1, c+2 pending)
            __syncthreads();        // all warps done with chunk c-1

            const int cc = c + 3;   // refill the slot chunk c-1 vacated
            if (cc < NCHUNK)
                load_chunk(sb + SM_CTRL + (cc & 3) * STAGE_BYTES,
                           A, B, m0, n0, cc * BK, tid);
            else if (has_next)
                load_chunk(sb + SM_CTRL + (cc & 3) * STAGE_BYTES,
                           A, B, m0n, n0n, (cc - NCHUNK) * BK, tid);
            else
                CP_COMMIT();        // empty group keeps accounting exact

            const uint32_t stage = sb + SM_CTRL + (c & 3) * STAGE_BYTES;
#pragma unroll
            for (int ks = 0; ks < 2; ks++) {
                uint32_t a[4][4], b[4][4];
#pragma unroll
                for (int mt = 0; mt < 4; mt++)
                    LDSM4(a[mt], stage + OFF_A + offA + mt * (16 * ROWB) + ks * 32);
#pragma unroll
                for (int bt = 0; bt < 4; bt++)
                    LDSM4(b[bt], stage + OFF_B + offB + bt * (16 * ROWB) + ks * 32);
#pragma unroll
                for (int mt = 0; mt < 4; mt++)
#pragma unroll
                    for (int nt = 0; nt < 8; nt++) {
                        const int bt = nt >> 1, sel = (nt & 1) * 2;
                        mma16816(acc[mt][nt], a[mt], b[bt][sel], b[bt][sel + 1]);
                    }
            }
        }

        // ---- epilogue: direct register -> global (overlaps next tile's loads)
        const int rbase = m0 + wm * 64 + (lane >> 2);
        const int cbase = n0 + wn * 64 + (lane & 3) * 2;
#pragma unroll
        for (int mt = 0; mt < 4; mt++)
#pragma unroll
            for (int nt = 0; nt < 8; nt++) {
                const int col = cbase + nt * 8;
#pragma unroll
                for (int h = 0; h < 2; h++) {
                    const int row = rbase + mt * 16 + h * 8;
                    float v0 = acc[mt][nt][h * 2 + 0] + bias_s[col + 0];
                    float v1 = acc[mt][nt][h * 2 + 1] + bias_s[col + 1];
                    const size_t e = (size_t)row * NDIM + col;
                    if (EPI == 1) {
                        *(__half2*)(outH + e) = __floats2half2_rn(ftanh(v0), ftanh(v1));
                    } else if (EPI == 2) {
                        *(__half2*)(outH + e) =
                            __floats2half2_rn(fmaxf(v0, 0.f), fmaxf(v1, 0.f));
                    } else if (EPI == 0) {
                        *(float2*)(outF + e) = make_float2(v0, v1);
                    } else {
                        const float2 nz = *(const float2*)(noise + e);
                        const float im0 = nz.x * fm_s[col + 0];
                        const float im1 = nz.y * fm_s[col + 1];
                        *(float4*)(outF + e * 4)       = make_float4(v0, im0, im0, im0);
                        *(float4*)(outF + (e + 1) * 4) = make_float4(v1, im1, im1, im1);
                    }
                }
            }

        if (!has_next) break;
        t = tn; m0 = m0n; n0 = n0n;
    }
}

// ---------------------------------------------------------------------------
// Merged prep: CTAs 0..1023 transpose+convert the 4 weights (one 32x32 tile
// each); CTAs 1024..3071 convert x -> fp16 (grid-stride).
// ---------------------------------------------------------------------------
__global__ void __launch_bounds__(256)
prep(const float* __restrict__ W1, const float* __restrict__ W2,
     const float* __restrict__ F1, const float* __restrict__ F2,
     __half* __restrict__ T,
     const float* __restrict__ x, __half* __restrict__ actA)
{
    const int tid = threadIdx.x;
    const int b   = blockIdx.x;

    if (b < 1024) {
        const int z   = b >> 8;             // which weight
        const int rem = b & 255;            // tile within it
        const float* W = (z == 0) ? W1 : (z == 1) ? W2 : (z == 2) ? F1 : F2;
        __half* Tz = T + (size_t)z * WSZ;

        __shared__ float tile[32][33];
        const int bx = (rem & 15) * 32, by = (rem >> 4) * 32;
        const int tx = tid & 31, ty = tid >> 5;   // 32 x 8
#pragma unroll
        for (int r = 0; r < 32; r += 8)
            tile[ty + r][tx] = W[(size_t)(by + ty + r) * NDIM + bx + tx];
        __syncthreads();
#pragma unroll
        for (int r = 0; r < 32; r += 8)
            Tz[(size_t)(bx + ty + r) * NDIM + by + tx] =
                __float2half_rn(tile[tx][ty + r]);
    } else {
        const int gt = (b - 1024) * 256 + tid;
        const int n4 = M_TOK * NDIM / 4;
#pragma unroll 2
        for (int i = gt; i < n4; i += 2048 * 256) {
            const float4 v = *(const float4*)(x + (size_t)i * 4);
            __half2* O = (__half2*)(actA + (size_t)i * 4);
            O[0] = __floats2half2_rn(v.x, v.y);
            O[1] = __floats2half2_rn(v.z, v.w);
        }
    }
}

// ---------------------------------------------------------------------------
// Kuramoto: 10 steps, first-order rotation (sn = s + c*d, cn = c - s*d).
// Amplitude drift <= (1+d^2/2)^10 ~ 1+1.1e-3; reaches output p only via
// a*c (a ~ 4e-4), so eps_p <~ 1e-5 -- negligible vs the 2e-4 fp16 floor.
// Inner loop: 4 FMA-class ops/elem/step (was 7).
// ---------------------------------------------------------------------------
__global__ void __launch_bounds__(256)
kuramoto_kernel(const float* __restrict__ P, const float* __restrict__ omega,
                const float* __restrict__ Kp, __half* __restrict__ outH)
{
    const int gwarp = (blockIdx.x * blockDim.x + threadIdx.x) >> 5;
    const int lane  = threadIdx.x & 31;
    if (gwarp >= M_TOK) return;

    const float* ph = P + (size_t)gwarp * NDIM;
    const float Kv = *Kp;
    const float a_scale = DT_C * Kv * (1.0f / (float)NDIM);

    float p[16], s[16], c[16], w[16];
#pragma unroll
    for (int i = 0; i < 16; i++) {
        const int e = lane + 32 * i;
        p[i] = ph[e];
        w[i] = DT_C * omega[e];
        __sincosf(p[i], &s[i], &c[i]);   // MUFU; |p| ~ O(3), err ~1e-6
    }
#pragma unroll 1
    for (int step = 0; step < NSTEPS; step++) {
        float part = 0.f;
#pragma unroll
        for (int i = 0; i < 16; i++) part += s[i];
#pragma unroll
        for (int off = 16; off > 0; off >>= 1)
            part += __shfl_xor_sync(0xFFFFFFFFu, part, off);
        const float a = a_scale * part;
#pragma unroll
        for (int i = 0; i < 16; i++) {
            const float d  = fmaf(a, c[i], w[i]);   // DT*(omega + K*m*cos)
            p[i] += d;
            const float sn = fmaf(c[i],  d, s[i]);  // first-order rotation
            const float cn = fmaf(-s[i], d, c[i]);
            s[i] = sn; c[i] = cn;
        }
    }
    const size_t base = (size_t)gwarp * NDIM;
#pragma unroll
    for (int i = 0; i < 16; i++)
        outH[base + lane + 32 * i] = __float2half_rn(p[i]);
}

// ---------------------------------------------------------------------------
extern "C" void kernel_launch(void* const* d_in, const int* in_sizes, int n_in,
                              void* d_out, int out_size)
{
    const float* x      = (const float*)d_in[0];
    const float* W1     = (const float*)d_in[1];
    const float* b1     = (const float*)d_in[2];
    const float* W2     = (const float*)d_in[3];
    const float* b2     = (const float*)d_in[4];
    const float* omega  = (const float*)d_in[5];
    const float* Kp     = (const float*)d_in[6];
    const float* alphap = (const float*)d_in[7];
    const float* F1     = (const float*)d_in[8];
    const float* c1     = (const float*)d_in[9];
    const float* F2     = (const float*)d_in[10];
    const float* c2     = (const float*)d_in[11];
    const float* noise  = (const float*)d_in[12];
    float* out = (float*)d_out;

    __half *actA, *actB, *wT;
    float* phb;
    cudaGetSymbolAddress((void**)&actA, g_act_a);
    cudaGetSymbolAddress((void**)&actB, g_act_b);
    cudaGetSymbolAddress((void**)&wT,   g_w);
    cudaGetSymbolAddress((void**)&phb,  g_ph);

    cudaFuncSetAttribute(gemm_f16<0>, cudaFuncAttributeMaxDynamicSharedMemorySize, GEMM_SMEM);
    cudaFuncSetAttribute(gemm_f16<1>, cudaFuncAttributeMaxDynamicSharedMemorySize, GEMM_SMEM);
    cudaFuncSetAttribute(gemm_f16<2>, cudaFuncAttributeMaxDynamicSharedMemorySize, GEMM_SMEM);
    cudaFuncSetAttribute(gemm_f16<3>, cudaFuncAttributeMaxDynamicSharedMemorySize, GEMM_SMEM);

    // prep: weights transpose (CTAs 0..1023) || x conversion (CTAs 1024..3071)
    prep<<<3072, 256>>>(W1, W2, F1, F2, wT, x, actA);

    // phases = tanh(x @ W1 + b1) -> fp16
    gemm_f16<1><<<NPERS, NTHR, GEMM_SMEM>>>(actA, wT + 0*WSZ,
                                            b1, actB, nullptr, nullptr, nullptr);
    // phases = phases @ W2 + b2 -> fp32
    gemm_f16<0><<<NPERS, NTHR, GEMM_SMEM>>>(actB, wT + 1*WSZ,
                                            b2, nullptr, phb, nullptr, nullptr);
    // Kuramoto -> fp16 phases
    kuramoto_kernel<<<M_TOK / 8, 256>>>(phb, omega, Kp, actA);
    // h = relu(phases @ F1 + c1) -> fp16
    gemm_f16<2><<<NPERS, NTHR, GEMM_SMEM>>>(actA, wT + 2*WSZ,
                                            c1, actB, nullptr, nullptr, nullptr);
    // out = expand(h @ F2 + c2, noise)
    gemm_f16<3><<<NPERS, NTHR, GEMM_SMEM>>>(actB, wT + 3*WSZ,
                                            c2, nullptr, out, noise, alphap);
}

// round 16
// speedup vs baseline: 1.2749x; 1.0170x over previous
#include <cuda_runtime.h>
#include <cuda_fp16.h>
#include <cstdint>
#include <math.h>

// ---------------------------------------------------------------------------
#define M_TOK 32768      // B*S
#define NDIM  512        // E = O
#define DT_C  0.01f
#define NSTEPS 10

#define BM 128
#define BN 128
#define BK 32
#define NCHUNK 16        // 512/32
#define NTHR 128         // 4 warps, warp tile 64x64 (measured-best config)
#define NSTAGE 4
#define NTILES ((M_TOK / BM) * (NDIM / BN))   // 1024
#define NPERS 304                              // 152 SMs x 2 resident CTAs
#define WSZ (NDIM * NDIM)

// smem: rows of 80B (64B data + 16B pad -> conflict-free ldmatrix)
#define ROWB 80
#define TILE_BYTES (128 * ROWB)            // 10240
#define OFF_A  0
#define OFF_B  TILE_BYTES
#define STAGE_BYTES (2 * TILE_BYTES)       // 20480 (A+B)
#define SM_CTRL 4608                       // pad + bias[512] + fm[512]
#define GEMM_SMEM (SM_CTRL + NSTAGE * STAGE_BYTES)   // 86528; x2 CTAs = 173KB

// ---------------------------------------------------------------------------
// Global scratch (allocation-free rule)
// ---------------------------------------------------------------------------
__device__ __half g_act_a[M_TOK*NDIM];   // activations ping
__device__ __half g_act_b[M_TOK*NDIM];   // activations pong
__device__ float  g_ph[M_TOK*NDIM];      // fp32 phases for Kuramoto
__device__ __half g_w[4*NDIM*NDIM];      // transposed fp16 weights

// ---------------------------------------------------------------------------
// PTX helpers (sm_80-era only)
// ---------------------------------------------------------------------------
static __device__ __forceinline__ uint32_t smem_u32(const void* p) {
    uint32_t a;
    asm("{ .reg .u64 t; cvta.to.shared.u64 t, %1; cvt.u32.u64 %0, t; }" : "=r"(a) : "l"(p));
    return a;
}
static __device__ __forceinline__ void cp16(uint32_t dst, const void* src) {
    asm volatile("cp.async.cg.shared.global [%0], [%1], 16;" :: "r"(dst), "l"(src));
}
#define CP_COMMIT() asm volatile("cp.async.commit_group;" ::: "memory")
#define CP_WAIT(n)  asm volatile("cp.async.wait_group %0;" :: "n"(n) : "memory")

#define LDSM4(r, addr) \
    asm volatile("ldmatrix.sync.aligned.m8n8.x4.shared.b16 {%0,%1,%2,%3}, [%4];" \
        : "=r"((r)[0]), "=r"((r)[1]), "=r"((r)[2]), "=r"((r)[3]) : "r"(addr))

static __device__ __forceinline__ void mma16816(float* c, const uint32_t* a,
                                                const uint32_t b0, const uint32_t b1) {
    asm volatile("mma.sync.aligned.m16n8k16.row.col.f32.f16.f16.f32 "
        "{%0,%1,%2,%3}, {%4,%5,%6,%7}, {%8,%9}, {%0,%1,%2,%3};"
        : "+f"(c[0]), "+f"(c[1]), "+f"(c[2]), "+f"(c[3])
        : "r"(a[0]), "r"(a[1]), "r"(a[2]), "r"(a[3]), "r"(b0), "r"(b1));
}

// fast tanh via MUFU: 1 - 2/(exp(2x)+1); saturates correctly at +-inf
static __device__ __forceinline__ float ftanh(float x) {
    float e, r;
    const float u = x * 2.8853900817779268f;   // 2*log2(e)
    asm("ex2.approx.f32 %0, %1;" : "=f"(e) : "f"(u));
    asm("rcp.approx.f32 %0, %1;" : "=f"(r) : "f"(e + 1.0f));
    return fmaf(-2.0f, r, 1.0f);
}

// ---------------------------------------------------------------------------
// Load one K-chunk: A 128x32 fp16 + B 128x32 fp16. 8 cp16/thread (128 thr).
// ---------------------------------------------------------------------------
static __device__ __forceinline__ void load_chunk(
    uint32_t stage,
    const __half* __restrict__ A, const __half* __restrict__ B,
    int m0, int n0, int kc0, int tid)
{
#pragma unroll
    for (int i = 0; i < 4; i++) {
        const int t   = tid + i * NTHR;      // 0..511
        const int row = t >> 2;              // 0..127
        const int q   = t & 3;
        const uint32_t so = (uint32_t)(row * ROWB + q * 16);
        cp16(stage + OFF_A + so, A + (size_t)(m0 + row) * NDIM + kc0 + q * 8);
        cp16(stage + OFF_B + so, B + (size_t)(n0 + row) * NDIM + kc0 + q * 8);
    }
    CP_COMMIT();
}

// ---------------------------------------------------------------------------
// Persistent fp16 GEMM (R10 engine, frozen): C[M,N] = act(A @ B^T + bias)
// CTA 128x128, 4 warps of 64x64, 4-stage cp.async ring continuous across tiles,
// static tile walk t += NPERS, direct register->global epilogue.
// EPI: 0 -> fp32 outF; 1 -> tanh fp16 outH; 2 -> relu fp16 outH;
//      3 -> final [m,n,4] {v, im, im, im}, im = noise*sin(alpha*n)
// ---------------------------------------------------------------------------
template<int EPI>
__global__ void __launch_bounds__(NTHR, 2)
gemm_f16(const __half* __restrict__ A, const __half* __restrict__ B,
         const float* __restrict__ bias,
         __half* __restrict__ outH, float* __restrict__ outF,
         const float* __restrict__ noise, const float* __restrict__ alpha_p)
{
    extern __shared__ char smem[];
    const uint32_t sb = smem_u32(smem);
    const int tid  = threadIdx.x;
    const int wid  = tid >> 5;
    const int lane = tid & 31;

    const int wm = wid & 1;        // 2 warps along M (64 rows each)
    const int wn = wid >> 1;       // 2 warps along N (64 cols each)

    float* bias_s = (float*)(smem + 64);      // 512 floats
    float* fm_s   = (float*)(smem + 2112);    // 512 floats
    {
        const float alpha = (EPI == 3) ? *alpha_p : 0.f;
#pragma unroll
        for (int i = tid; i < NDIM; i += NTHR) {
            bias_s[i] = bias[i];
            if (EPI == 3) fm_s[i] = sinf(alpha * (float)i);
        }
    }

    int t  = blockIdx.x;
    int m0 = (t >> 2) * BM;
    int n0 = (t & 3) * BN;

    // prologue: 3 chunk-loads of first tile in flight
    load_chunk(sb + SM_CTRL + 0 * STAGE_BYTES, A, B, m0, n0, 0 * BK, tid);
    load_chunk(sb + SM_CTRL + 1 * STAGE_BYTES, A, B, m0, n0, 1 * BK, tid);
    load_chunk(sb + SM_CTRL + 2 * STAGE_BYTES, A, B, m0, n0, 2 * BK, tid);

    const int g  = lane >> 3;
    const int lr = lane & 7;
    const uint32_t offA = (uint32_t)((wm * 64 + (g & 1) * 8 + lr) * ROWB + (g >> 1) * 16);
    const uint32_t offB = (uint32_t)((wn * 64 + (g >> 1) * 8 + lr) * ROWB + (g & 1) * 16);

    while (true) {
        const int tn  = t + NPERS;
        const bool has_next = (tn < NTILES);
        const int m0n = (tn >> 2) * BM;
        const int n0n = (tn & 3) * BN;

        float acc[4][8][4];
#pragma unroll
        for (int mt = 0; mt < 4; mt++)
#pragma unroll
            for (int nt = 0; nt < 8; nt++)
#pragma unroll
                for (int r = 0; r < 4; r++) acc[mt][nt][r] = 0.f;

#pragma unroll 1
        for (int c = 0; c < NCHUNK; c++) {
            CP_WAIT(2);             // chunk c landed (c+1, c+2 pending)
            __syncthreads();        // all warps done with chunk c-1

            const int cc = c + 3;   // refill the slot chunk c-1 vacated
            if (cc < NCHUNK)
                load_chunk(sb + SM_CTRL + (cc & 3) * STAGE_BYTES,
                           A, B, m0, n0, cc * BK, tid);
            else if (has_next)
                load_chunk(sb + SM_CTRL + (cc & 3) * STAGE_BYTES,
                           A, B, m0n, n0n, (cc - NCHUNK) * BK, tid);
            else
                CP_COMMIT();        // empty group keeps accounting exact

            const uint32_t stage = sb + SM_CTRL + (c & 3) * STAGE_BYTES;
#pragma unroll
            for (int ks = 0; ks < 2; ks++) {
                uint32_t a[4][4], b[4][4];
#pragma unroll
                for (int mt = 0; mt < 4; mt++)
                    LDSM4(a[mt], stage + OFF_A + offA + mt * (16 * ROWB) + ks * 32);
#pragma unroll
                for (int bt = 0; bt < 4; bt++)
                    LDSM4(b[bt], stage + OFF_B + offB + bt * (16 * ROWB) + ks * 32);
#pragma unroll
                for (int mt = 0; mt < 4; mt++)
#pragma unroll
                    for (int nt = 0; nt < 8; nt++) {
                        const int bt = nt >> 1, sel = (nt & 1) * 2;
                        mma16816(acc[mt][nt], a[mt], b[bt][sel], b[bt][sel + 1]);
                    }
            }
        }

        // ---- epilogue: direct register -> global (overlaps next tile's loads)
        const int rbase = m0 + wm * 64 + (lane >> 2);
        const int cbase = n0 + wn * 64 + (lane & 3) * 2;
#pragma unroll
        for (int mt = 0; mt < 4; mt++)
#pragma unroll
            for (int nt = 0; nt < 8; nt++) {
                const int col = cbase + nt * 8;
#pragma unroll
                for (int h = 0; h < 2; h++) {
                    const int row = rbase + mt * 16 + h * 8;
                    float v0 = acc[mt][nt][h * 2 + 0] + bias_s[col + 0];
                    float v1 = acc[mt][nt][h * 2 + 1] + bias_s[col + 1];
                    const size_t e = (size_t)row * NDIM + col;
                    if (EPI == 1) {
                        *(__half2*)(outH + e) = __floats2half2_rn(ftanh(v0), ftanh(v1));
                    } else if (EPI == 2) {
                        *(__half2*)(outH + e) =
                            __floats2half2_rn(fmaxf(v0, 0.f), fmaxf(v1, 0.f));
                    } else if (EPI == 0) {
                        *(float2*)(outF + e) = make_float2(v0, v1);
                    } else {
                        const float2 nz = *(const float2*)(noise + e);
                        const float im0 = nz.x * fm_s[col + 0];
                        const float im1 = nz.y * fm_s[col + 1];
                        *(float4*)(outF + e * 4)       = make_float4(v0, im0, im0, im0);
                        *(float4*)(outF + (e + 1) * 4) = make_float4(v1, im1, im1, im1);
                    }
                }
            }

        if (!has_next) break;
        t = tn; m0 = m0n; n0 = n0n;
    }
}

// ---------------------------------------------------------------------------
// Merged prep: CTAs 0..1023 transpose+convert the 4 weights (one 32x32 tile
// each); CTAs 1024..3071 convert x -> fp16 (grid-stride).
// ---------------------------------------------------------------------------
__global__ void __launch_bounds__(256)
prep(const float* __restrict__ W1, const float* __restrict__ W2,
     const float* __restrict__ F1, const float* __restrict__ F2,
     __half* __restrict__ T,
     const float* __restrict__ x, __half* __restrict__ actA)
{
    const int tid = threadIdx.x;
    const int b   = blockIdx.x;

    if (b < 1024) {
        const int z   = b >> 8;             // which weight
        const int rem = b & 255;            // tile within it
        const float* W = (z == 0) ? W1 : (z == 1) ? W2 : (z == 2) ? F1 : F2;
        __half* Tz = T + (size_t)z * WSZ;

        __shared__ float tile[32][33];
        const int bx = (rem & 15) * 32, by = (rem >> 4) * 32;
        const int tx = tid & 31, ty = tid >> 5;   // 32 x 8
#pragma unroll
        for (int r = 0; r < 32; r += 8)
            tile[ty + r][tx] = W[(size_t)(by + ty + r) * NDIM + bx + tx];
        __syncthreads();
#pragma unroll
        for (int r = 0; r < 32; r += 8)
            Tz[(size_t)(bx + ty + r) * NDIM + by + tx] =
                __float2half_rn(tile[tx][ty + r]);
    } else {
        const int gt = (b - 1024) * 256 + tid;
        const int n4 = M_TOK * NDIM / 4;
#pragma unroll 2
        for (int i = gt; i < n4; i += 2048 * 256) {
            const float4 v = *(const float4*)(x + (size_t)i * 4);
            __half2* O = (__half2*)(actA + (size_t)i * 4);
            O[0] = __floats2half2_rn(v.x, v.y);
            O[1] = __floats2half2_rn(v.z, v.w);
        }
    }
}

// ---------------------------------------------------------------------------
// Kuramoto: 10 steps, first-order rotation, pairwise-tree partial sum.
// 128 threads, min 6 CTAs/SM (caps regs at 85) -> 24 warps/SM residency.
// ---------------------------------------------------------------------------
__global__ void __launch_bounds__(128, 6)
kuramoto_kernel(const float* __restrict__ P, const float* __restrict__ omega,
                const float* __restrict__ Kp, __half* __restrict__ outH)
{
    const int gwarp = (blockIdx.x * blockDim.x + threadIdx.x) >> 5;
    const int lane  = threadIdx.x & 31;
    if (gwarp >= M_TOK) return;

    const float* ph = P + (size_t)gwarp * NDIM;
    const float Kv = *Kp;
    const float a_scale = DT_C * Kv * (1.0f / (float)NDIM);

    float p[16], s[16], c[16], w[16];
#pragma unroll
    for (int i = 0; i < 16; i++) {
        const int e = lane + 32 * i;
        p[i] = ph[e];
        w[i] = DT_C * omega[e];
        __sincosf(p[i], &s[i], &c[i]);   // MUFU; |p| ~ O(3), err ~1e-6
    }
#pragma unroll 1
    for (int step = 0; step < NSTEPS; step++) {
        // pairwise tree: depth 4 instead of serial 16-add chain
        float t8[8];
#pragma unroll
        for (int i = 0; i < 8; i++) t8[i] = s[2 * i] + s[2 * i + 1];
        float t4[4];
#pragma unroll
        for (int i = 0; i < 4; i++) t4[i] = t8[2 * i] + t8[2 * i + 1];
        float part = (t4[0] + t4[1]) + (t4[2] + t4[3]);
#pragma unroll
        for (int off = 16; off > 0; off >>= 1)
            part += __shfl_xor_sync(0xFFFFFFFFu, part, off);
        const float a = a_scale * part;
#pragma unroll
        for (int i = 0; i < 16; i++) {
            const float d  = fmaf(a, c[i], w[i]);   // DT*(omega + K*m*cos)
            p[i] += d;
            const float sn = fmaf(c[i],  d, s[i]);  // first-order rotation
            const float cn = fmaf(-s[i], d, c[i]);
            s[i] = sn; c[i] = cn;
        }
    }
    const size_t base = (size_t)gwarp * NDIM;
#pragma unroll
    for (int i = 0; i < 16; i++)
        outH[base + lane + 32 * i] = __float2half_rn(p[i]);
}

// ---------------------------------------------------------------------------
extern "C" void kernel_launch(void* const* d_in, const int* in_sizes, int n_in,
                              void* d_out, int out_size)
{
    const float* x      = (const float*)d_in[0];
    const float* W1     = (const float*)d_in[1];
    const float* b1     = (const float*)d_in[2];
    const float* W2     = (const float*)d_in[3];
    const float* b2     = (const float*)d_in[4];
    const float* omega  = (const float*)d_in[5];
    const float* Kp     = (const float*)d_in[6];
    const float* alphap = (const float*)d_in[7];
    const float* F1     = (const float*)d_in[8];
    const float* c1     = (const float*)d_in[9];
    const float* F2     = (const float*)d_in[10];
    const float* c2     = (const float*)d_in[11];
    const float* noise  = (const float*)d_in[12];
    float* out = (float*)d_out;

    __half *actA, *actB, *wT;
    float* phb;
    cudaGetSymbolAddress((void**)&actA, g_act_a);
    cudaGetSymbolAddress((void**)&actB, g_act_b);
    cudaGetSymbolAddress((void**)&wT,   g_w);
    cudaGetSymbolAddress((void**)&phb,  g_ph);

    cudaFuncSetAttribute(gemm_f16<0>, cudaFuncAttributeMaxDynamicSharedMemorySize, GEMM_SMEM);
    cudaFuncSetAttribute(gemm_f16<1>, cudaFuncAttributeMaxDynamicSharedMemorySize, GEMM_SMEM);
    cudaFuncSetAttribute(gemm_f16<2>, cudaFuncAttributeMaxDynamicSharedMemorySize, GEMM_SMEM);
    cudaFuncSetAttribute(gemm_f16<3>, cudaFuncAttributeMaxDynamicSharedMemorySize, GEMM_SMEM);

    // prep: weights transpose (CTAs 0..1023) || x conversion (CTAs 1024..3071)
    prep<<<3072, 256>>>(W1, W2, F1, F2, wT, x, actA);

    // phases = tanh(x @ W1 + b1) -> fp16
    gemm_f16<1><<<NPERS, NTHR, GEMM_SMEM>>>(actA, wT + 0*WSZ,
                                            b1, actB, nullptr, nullptr, nullptr);
    // phases = phases @ W2 + b2 -> fp32
    gemm_f16<0><<<NPERS, NTHR, GEMM_SMEM>>>(actB, wT + 1*WSZ,
                                            b2, nullptr, phb, nullptr, nullptr);
    // Kuramoto -> fp16 phases (128-thread blocks, 4 warps each)
    kuramoto_kernel<<<M_TOK / 4, 128>>>(phb, omega, Kp, actA);
    // h = relu(phases @ F1 + c1) -> fp16
    gemm_f16<2><<<NPERS, NTHR, GEMM_SMEM>>>(actA, wT + 2*WSZ,
                                            c1, actB, nullptr, nullptr, nullptr);
    // out = expand(h @ F2 + c2, noise)
    gemm_f16<3><<<NPERS, NTHR, GEMM_SMEM>>>(actB, wT + 3*WSZ,
                                            c2, nullptr, out, noise, alphap);
}

// round 17
// speedup vs baseline: 1.2912x; 1.0128x over previous
#include <cuda_runtime.h>
#include <cuda_fp16.h>
#include <cstdint>
#include <math.h>

// ---------------------------------------------------------------------------
#define M_TOK 32768      // B*S
#define NDIM  512        // E = O
#define DT_C  0.01f
#define NSTEPS 10

#define BM 128
#define BN 128
#define BK 32
#define NCHUNK 16        // 512/32
#define NTHR 128         // 4 warps, warp tile 64x64 (measured-best config)
#define NSTAGE 4
#define NTILES ((M_TOK / BM) * (NDIM / BN))   // 1024
#define NPERS 304                              // 152 SMs x 2 resident CTAs
#define WSZ (NDIM * NDIM)

// smem: rows of 80B (64B data + 16B pad -> conflict-free ldmatrix)
#define ROWB 80
#define TILE_BYTES (128 * ROWB)            // 10240
#define OFF_A  0
#define OFF_B  TILE_BYTES
#define STAGE_BYTES (2 * TILE_BYTES)       // 20480 (A+B)
#define SM_CTRL 4608                       // pad + bias[512] + fm[512]
#define GEMM_SMEM (SM_CTRL + NSTAGE * STAGE_BYTES)   // 86528; x2 CTAs = 173KB

// ---------------------------------------------------------------------------
// Global scratch (allocation-free rule)
// ---------------------------------------------------------------------------
__device__ __half g_act_a[M_TOK*NDIM];   // activations ping
__device__ __half g_act_b[M_TOK*NDIM];   // activations pong
__device__ float  g_ph[M_TOK*NDIM];      // fp32 phases for Kuramoto
__device__ __half g_w[4*NDIM*NDIM];      // transposed fp16 weights

// ---------------------------------------------------------------------------
// PTX helpers (sm_80-era only)
// ---------------------------------------------------------------------------
static __device__ __forceinline__ uint32_t smem_u32(const void* p) {
    uint32_t a;
    asm("{ .reg .u64 t; cvta.to.shared.u64 t, %1; cvt.u32.u64 %0, t; }" : "=r"(a) : "l"(p));
    return a;
}
static __device__ __forceinline__ void cp16(uint32_t dst, const void* src) {
    asm volatile("cp.async.cg.shared.global [%0], [%1], 16;" :: "r"(dst), "l"(src));
}
#define CP_COMMIT() asm volatile("cp.async.commit_group;" ::: "memory")
#define CP_WAIT(n)  asm volatile("cp.async.wait_group %0;" :: "n"(n) : "memory")

#define LDSM4(r, addr) \
    asm volatile("ldmatrix.sync.aligned.m8n8.x4.shared.b16 {%0,%1,%2,%3}, [%4];" \
        : "=r"((r)[0]), "=r"((r)[1]), "=r"((r)[2]), "=r"((r)[3]) : "r"(addr))

static __device__ __forceinline__ void mma16816(float* c, const uint32_t* a,
                                                const uint32_t b0, const uint32_t b1) {
    asm volatile("mma.sync.aligned.m16n8k16.row.col.f32.f16.f16.f32 "
        "{%0,%1,%2,%3}, {%4,%5,%6,%7}, {%8,%9}, {%0,%1,%2,%3};"
        : "+f"(c[0]), "+f"(c[1]), "+f"(c[2]), "+f"(c[3])
        : "r"(a[0]), "r"(a[1]), "r"(a[2]), "r"(a[3]), "r"(b0), "r"(b1));
}

// fast tanh via MUFU: 1 - 2/(exp(2x)+1); saturates correctly at +-inf
static __device__ __forceinline__ float ftanh(float x) {
    float e, r;
    const float u = x * 2.8853900817779268f;   // 2*log2(e)
    asm("ex2.approx.f32 %0, %1;" : "=f"(e) : "f"(u));
    asm("rcp.approx.f32 %0, %1;" : "=f"(r) : "f"(e + 1.0f));
    return fmaf(-2.0f, r, 1.0f);
}

// ---------------------------------------------------------------------------
// Load one K-chunk: A 128x32 fp16 + B 128x32 fp16. 8 cp16/thread (128 thr).
// ---------------------------------------------------------------------------
static __device__ __forceinline__ void load_chunk(
    uint32_t stage,
    const __half* __restrict__ A, const __half* __restrict__ B,
    int m0, int n0, int kc0, int tid)
{
#pragma unroll
    for (int i = 0; i < 4; i++) {
        const int t   = tid + i * NTHR;      // 0..511
        const int row = t >> 2;              // 0..127
        const int q   = t & 3;
        const uint32_t so = (uint32_t)(row * ROWB + q * 16);
        cp16(stage + OFF_A + so, A + (size_t)(m0 + row) * NDIM + kc0 + q * 8);
        cp16(stage + OFF_B + so, B + (size_t)(n0 + row) * NDIM + kc0 + q * 8);
    }
    CP_COMMIT();
}

// ---------------------------------------------------------------------------
// Persistent fp16 GEMM (R10 engine, frozen): C[M,N] = act(A @ B^T + bias)
// CTA 128x128, 4 warps of 64x64, 4-stage cp.async ring continuous across tiles,
// static tile walk t += NPERS, direct register->global epilogue.
// EPI: 0 -> fp32 outF; 1 -> tanh fp16 outH; 2 -> relu fp16 outH;
//      3 -> final [m,n,4] {v, im, im, im}, im = noise*sin(alpha*n)
// ---------------------------------------------------------------------------
template<int EPI>
__global__ void __launch_bounds__(NTHR, 2)
gemm_f16(const __half* __restrict__ A, const __half* __restrict__ B,
         const float* __restrict__ bias,
         __half* __restrict__ outH, float* __restrict__ outF,
         const float* __restrict__ noise, const float* __restrict__ alpha_p)
{
    extern __shared__ char smem[];
    const uint32_t sb = smem_u32(smem);
    const int tid  = threadIdx.x;
    const int wid  = tid >> 5;
    const int lane = tid & 31;

    const int wm = wid & 1;        // 2 warps along M (64 rows each)
    const int wn = wid >> 1;       // 2 warps along N (64 cols each)

    float* bias_s = (float*)(smem + 64);      // 512 floats
    float* fm_s   = (float*)(smem + 2112);    // 512 floats
    {
        const float alpha = (EPI == 3) ? *alpha_p : 0.f;
#pragma unroll
        for (int i = tid; i < NDIM; i += NTHR) {
            bias_s[i] = bias[i];
            if (EPI == 3) fm_s[i] = sinf(alpha * (float)i);
        }
    }

    int t  = blockIdx.x;
    int m0 = (t >> 2) * BM;
    int n0 = (t & 3) * BN;

    // prologue: 3 chunk-loads of first tile in flight
    load_chunk(sb + SM_CTRL + 0 * STAGE_BYTES, A, B, m0, n0, 0 * BK, tid);
    load_chunk(sb + SM_CTRL + 1 * STAGE_BYTES, A, B, m0, n0, 1 * BK, tid);
    load_chunk(sb + SM_CTRL + 2 * STAGE_BYTES, A, B, m0, n0, 2 * BK, tid);

    const int g  = lane >> 3;
    const int lr = lane & 7;
    const uint32_t offA = (uint32_t)((wm * 64 + (g & 1) * 8 + lr) * ROWB + (g >> 1) * 16);
    const uint32_t offB = (uint32_t)((wn * 64 + (g >> 1) * 8 + lr) * ROWB + (g & 1) * 16);

    while (true) {
        const int tn  = t + NPERS;
        const bool has_next = (tn < NTILES);
        const int m0n = (tn >> 2) * BM;
        const int n0n = (tn & 3) * BN;

        float acc[4][8][4];
#pragma unroll
        for (int mt = 0; mt < 4; mt++)
#pragma unroll
            for (int nt = 0; nt < 8; nt++)
#pragma unroll
                for (int r = 0; r < 4; r++) acc[mt][nt][r] = 0.f;

#pragma unroll 1
        for (int c = 0; c < NCHUNK; c++) {
            CP_WAIT(2);             // chunk c landed (c+1, c+2 pending)
            __syncthreads();        // all warps done with chunk c-1

            const int cc = c + 3;   // refill the slot chunk c-1 vacated
            if (cc < NCHUNK)
                load_chunk(sb + SM_CTRL + (cc & 3) * STAGE_BYTES,
                           A, B, m0, n0, cc * BK, tid);
            else if (has_next)
                load_chunk(sb + SM_CTRL + (cc & 3) * STAGE_BYTES,
                           A, B, m0n, n0n, (cc - NCHUNK) * BK, tid);
            else
                CP_COMMIT();        // empty group keeps accounting exact

            const uint32_t stage = sb + SM_CTRL + (c & 3) * STAGE_BYTES;
#pragma unroll
            for (int ks = 0; ks < 2; ks++) {
                uint32_t a[4][4], b[4][4];
#pragma unroll
                for (int mt = 0; mt < 4; mt++)
                    LDSM4(a[mt], stage + OFF_A + offA + mt * (16 * ROWB) + ks * 32);
#pragma unroll
                for (int bt = 0; bt < 4; bt++)
                    LDSM4(b[bt], stage + OFF_B + offB + bt * (16 * ROWB) + ks * 32);
#pragma unroll
                for (int mt = 0; mt < 4; mt++)
#pragma unroll
                    for (int nt = 0; nt < 8; nt++) {
                        const int bt = nt >> 1, sel = (nt & 1) * 2;
                        mma16816(acc[mt][nt], a[mt], b[bt][sel], b[bt][sel + 1]);
                    }
            }
        }

        // ---- epilogue: direct register -> global (overlaps next tile's loads)
        const int rbase = m0 + wm * 64 + (lane >> 2);
        const int cbase = n0 + wn * 64 + (lane & 3) * 2;
#pragma unroll
        for (int mt = 0; mt < 4; mt++)
#pragma unroll
            for (int nt = 0; nt < 8; nt++) {
                const int col = cbase + nt * 8;
#pragma unroll
                for (int h = 0; h < 2; h++) {
                    const int row = rbase + mt * 16 + h * 8;
                    float v0 = acc[mt][nt][h * 2 + 0] + bias_s[col + 0];
                    float v1 = acc[mt][nt][h * 2 + 1] + bias_s[col + 1];
                    const size_t e = (size_t)row * NDIM + col;
                    if (EPI == 1) {
                        *(__half2*)(outH + e) = __floats2half2_rn(ftanh(v0), ftanh(v1));
                    } else if (EPI == 2) {
                        *(__half2*)(outH + e) =
                            __floats2half2_rn(fmaxf(v0, 0.f), fmaxf(v1, 0.f));
                    } else if (EPI == 0) {
                        *(float2*)(outF + e) = make_float2(v0, v1);
                    } else {
                        const float2 nz = *(const float2*)(noise + e);
                        const float im0 = nz.x * fm_s[col + 0];
                        const float im1 = nz.y * fm_s[col + 1];
                        *(float4*)(outF + e * 4)       = make_float4(v0, im0, im0, im0);
                        *(float4*)(outF + (e + 1) * 4) = make_float4(v1, im1, im1, im1);
                    }
                }
            }

        if (!has_next) break;
        t = tn; m0 = m0n; n0 = n0n;
    }
}

// ---------------------------------------------------------------------------
// Merged prep: CTAs 0..1023 transpose+convert the 4 weights (one 32x32 tile
// each); CTAs 1024..3071 convert x -> fp16 (grid-stride).
// ---------------------------------------------------------------------------
__global__ void __launch_bounds__(256)
prep(const float* __restrict__ W1, const float* __restrict__ W2,
     const float* __restrict__ F1, const float* __restrict__ F2,
     __half* __restrict__ T,
     const float* __restrict__ x, __half* __restrict__ actA)
{
    const int tid = threadIdx.x;
    const int b   = blockIdx.x;

    if (b < 1024) {
        const int z   = b >> 8;             // which weight
        const int rem = b & 255;            // tile within it
        const float* W = (z == 0) ? W1 : (z == 1) ? W2 : (z == 2) ? F1 : F2;
        __half* Tz = T + (size_t)z * WSZ;

        __shared__ float tile[32][33];
        const int bx = (rem & 15) * 32, by = (rem >> 4) * 32;
        const int tx = tid & 31, ty = tid >> 5;   // 32 x 8
#pragma unroll
        for (int r = 0; r < 32; r += 8)
            tile[ty + r][tx] = W[(size_t)(by + ty + r) * NDIM + bx + tx];
        __syncthreads();
#pragma unroll
        for (int r = 0; r < 32; r += 8)
            Tz[(size_t)(bx + ty + r) * NDIM + by + tx] =
                __float2half_rn(tile[tx][ty + r]);
    } else {
        const int gt = (b - 1024) * 256 + tid;
        const int n4 = M_TOK * NDIM / 4;
#pragma unroll 2
        for (int i = gt; i < n4; i += 2048 * 256) {
            const float4 v = *(const float4*)(x + (size_t)i * 4);
            __half2* O = (__half2*)(actA + (size_t)i * 4);
            O[0] = __floats2half2_rn(v.x, v.y);
            O[1] = __floats2half2_rn(v.z, v.w);
        }
    }
}

// ---------------------------------------------------------------------------
// Kuramoto: 2 independent tokens per warp (interleaved chains hide the
// SHFL-reduction latency), first-order rotation, pairwise-tree partial sums.
// p/s/c x2 tokens = 96 regs + shared w[16]; __launch_bounds__(128,4) caps 128.
// ---------------------------------------------------------------------------
__global__ void __launch_bounds__(128, 4)
kuramoto_kernel(const float* __restrict__ P, const float* __restrict__ omega,
                const float* __restrict__ Kp, __half* __restrict__ outH)
{
    const int gwarp = (blockIdx.x * blockDim.x + threadIdx.x) >> 5;
    const int lane  = threadIdx.x & 31;
    const int tok0  = gwarp * 2;
    if (tok0 >= M_TOK) return;

    const float* ph0 = P + (size_t)tok0 * NDIM;
    const float* ph1 = ph0 + NDIM;
    const float Kv = *Kp;
    const float a_scale = DT_C * Kv * (1.0f / (float)NDIM);

    float w[16];
    float p0[16], s0[16], c0[16];
    float p1[16], s1[16], c1[16];
#pragma unroll
    for (int i = 0; i < 16; i++) {
        const int e = lane + 32 * i;
        w[i]  = DT_C * omega[e];            // element-indexed, token-invariant
        p0[i] = ph0[e];
        p1[i] = ph1[e];
        __sincosf(p0[i], &s0[i], &c0[i]);
        __sincosf(p1[i], &s1[i], &c1[i]);
    }
#pragma unroll 1
    for (int step = 0; step < NSTEPS; step++) {
        // two independent pairwise trees + shfl chains (interleaved by HW)
        float ta[8], tb[8];
#pragma unroll
        for (int i = 0; i < 8; i++) {
            ta[i] = s0[2 * i] + s0[2 * i + 1];
            tb[i] = s1[2 * i] + s1[2 * i + 1];
        }
        float ua[4], ub[4];
#pragma unroll
        for (int i = 0; i < 4; i++) {
            ua[i] = ta[2 * i] + ta[2 * i + 1];
            ub[i] = tb[2 * i] + tb[2 * i + 1];
        }
        float pa = (ua[0] + ua[1]) + (ua[2] + ua[3]);
        float pb = (ub[0] + ub[1]) + (ub[2] + ub[3]);
#pragma unroll
        for (int off = 16; off > 0; off >>= 1) {
            pa += __shfl_xor_sync(0xFFFFFFFFu, pa, off);
            pb += __shfl_xor_sync(0xFFFFFFFFu, pb, off);
        }
        const float a0 = a_scale * pa;
        const float a1 = a_scale * pb;
#pragma unroll
        for (int i = 0; i < 16; i++) {
            const float d0 = fmaf(a0, c0[i], w[i]);
            const float d1 = fmaf(a1, c1[i], w[i]);
            p0[i] += d0;
            p1[i] += d1;
            const float sn0 = fmaf(c0[i],  d0, s0[i]);
            const float cn0 = fmaf(-s0[i], d0, c0[i]);
            const float sn1 = fmaf(c1[i],  d1, s1[i]);
            const float cn1 = fmaf(-s1[i], d1, c1[i]);
            s0[i] = sn0; c0[i] = cn0;
            s1[i] = sn1; c1[i] = cn1;
        }
    }
    __half* oh0 = outH + (size_t)tok0 * NDIM;
    __half* oh1 = oh0 + NDIM;
#pragma unroll
    for (int i = 0; i < 16; i++) {
        oh0[lane + 32 * i] = __float2half_rn(p0[i]);
        oh1[lane + 32 * i] = __float2half_rn(p1[i]);
    }
}

// ---------------------------------------------------------------------------
extern "C" void kernel_launch(void* const* d_in, const int* in_sizes, int n_in,
                              void* d_out, int out_size)
{
    const float* x      = (const float*)d_in[0];
    const float* W1     = (const float*)d_in[1];
    const float* b1     = (const float*)d_in[2];
    const float* W2     = (const float*)d_in[3];
    const float* b2     = (const float*)d_in[4];
    const float* omega  = (const float*)d_in[5];
    const float* Kp     = (const float*)d_in[6];
    const float* alphap = (const float*)d_in[7];
    const float* F1     = (const float*)d_in[8];
    const float* c1     = (const float*)d_in[9];
    const float* F2     = (const float*)d_in[10];
    const float* c2     = (const float*)d_in[11];
    const float* noise  = (const float*)d_in[12];
    float* out = (float*)d_out;

    __half *actA, *actB, *wT;
    float* phb;
    cudaGetSymbolAddress((void**)&actA, g_act_a);
    cudaGetSymbolAddress((void**)&actB, g_act_b);
    cudaGetSymbolAddress((void**)&wT,   g_w);
    cudaGetSymbolAddress((void**)&phb,  g_ph);

    cudaFuncSetAttribute(gemm_f16<0>, cudaFuncAttributeMaxDynamicSharedMemorySize, GEMM_SMEM);
    cudaFuncSetAttribute(gemm_f16<1>, cudaFuncAttributeMaxDynamicSharedMemorySize, GEMM_SMEM);
    cudaFuncSetAttribute(gemm_f16<2>, cudaFuncAttributeMaxDynamicSharedMemorySize, GEMM_SMEM);
    cudaFuncSetAttribute(gemm_f16<3>, cudaFuncAttributeMaxDynamicSharedMemorySize, GEMM_SMEM);

    // prep: weights transpose (CTAs 0..1023) || x conversion (CTAs 1024..3071)
    prep<<<3072, 256>>>(W1, W2, F1, F2, wT, x, actA);

    // phases = tanh(x @ W1 + b1) -> fp16
    gemm_f16<1><<<NPERS, NTHR, GEMM_SMEM>>>(actA, wT + 0*WSZ,
                                            b1, actB, nullptr, nullptr, nullptr);
    // phases = phases @ W2 + b2 -> fp32
    gemm_f16<0><<<NPERS, NTHR, GEMM_SMEM>>>(actB, wT + 1*WSZ,
                                            b2, nullptr, phb, nullptr, nullptr);
    // Kuramoto -> fp16 phases (2 tokens per warp, 4096 blocks of 128)
    kuramoto_kernel<<<M_TOK / 8, 128>>>(phb, omega, Kp, actA);
    // h = relu(phases @ F1 + c1) -> fp16
    gemm_f16<2><<<NPERS, NTHR, GEMM_SMEM>>>(actA, wT + 2*WSZ,
                                            c1, actB, nullptr, nullptr, nullptr);
    // out = expand(h @ F2 + c2, noise)
    gemm_f16<3><<<NPERS, NTHR, GEMM_SMEM>>>(actB, wT + 3*WSZ,
                                            c2, nullptr, out, noise, alphap);
}